// round 16
// baseline (speedup 1.0000x reference)
#include <cuda_runtime.h>
#include <cstdint>

// RoiPoolingConv: img [1,256,256,512] f32 (NHWC), rois [1,1024,4] i32 (x1,y1,x2,y2)
// out [1,1024,7,7,512] f32 — TF1-legacy bilinear crop-resize to 7x7.
//
// R15: completes the L2-residency experiment. R14 showed evict_last reads
// alone give zero retention — hypothesis: __stcs (.cs legacy) is a no-op for
// Blackwell L2, so the 103 MB/replay write stream allocates at normal
// priority and cycles the whole cache, evicting the read set. Fix: stores
// use the real mechanism too — st.global.L2::evict_first.v8.b32 (256-bit,
// 32 B/thread). Reads (evict_last, ~98 MB deduped set) should then persist
// in L2 (126 MB) across graph replays; writes wash through.
// Body = R14: 64 thr x 32 B, block per (roi,py) row, tap dedup, full unroll.

#define POOL 7
#define IMG_W 256
#define IMG_C 512
#define NV8 (IMG_C / 8)   // 64 threads, 8 floats (32 B) each

struct f8 { float v[8]; };

// 256-bit read-only global load with L2 evict-last (preferred-keep) hint.
__device__ __forceinline__ f8 ldg_keep(const float* p)
{
    uint32_t a, b, c, d, e, f, g, h;
    asm("ld.global.nc.L2::evict_last.v8.b32 {%0,%1,%2,%3,%4,%5,%6,%7}, [%8];"
        : "=r"(a), "=r"(b), "=r"(c), "=r"(d),
          "=r"(e), "=r"(f), "=r"(g), "=r"(h)
        : "l"(p));
    f8 o;
    o.v[0] = __uint_as_float(a); o.v[1] = __uint_as_float(b);
    o.v[2] = __uint_as_float(c); o.v[3] = __uint_as_float(d);
    o.v[4] = __uint_as_float(e); o.v[5] = __uint_as_float(f);
    o.v[6] = __uint_as_float(g); o.v[7] = __uint_as_float(h);
    return o;
}

// 256-bit global store with L2 evict-first hint: write stream washes
// through L2 without displacing the resident read set.
__device__ __forceinline__ void stg_wash(float* p, const float o[8])
{
    asm volatile(
        "st.global.L2::evict_first.v8.b32 [%0], {%1,%2,%3,%4,%5,%6,%7,%8};"
        :: "l"(p),
           "r"(__float_as_uint(o[0])), "r"(__float_as_uint(o[1])),
           "r"(__float_as_uint(o[2])), "r"(__float_as_uint(o[3])),
           "r"(__float_as_uint(o[4])), "r"(__float_as_uint(o[5])),
           "r"(__float_as_uint(o[6])), "r"(__float_as_uint(o[7]))
        : "memory");
}

__global__ __launch_bounds__(NV8, 16)
void roi_pool_row_kernel(const float* __restrict__ img,
                         const int*   __restrict__ rois,
                         float*       __restrict__ out)
{
    const int py  = blockIdx.x;          // 0..6
    const int roi = blockIdx.y;          // 0..1023

    // ROI descriptor: 16B aligned, uniform across block
    const int4 r = __ldg(reinterpret_cast<const int4*>(rois) + roi);
    const int x1 = r.x, y1 = r.y, x2 = r.z, y2 = r.w;

    const int hi = y2 - y1;
    const int wi = x2 - x1;
    const float h = (float)hi;
    const float w = (float)wi;

    // Reference op order: (h / P) first, then scale by index.
    const float ys = (float)py * (h / 7.0f);
    const int   y0 = (int)floorf(ys);
    const int ymax = max(hi - 1, 0);
    const int xmax = max(wi - 1, 0);
    const int  y1i = min(y0 + 1, ymax);
    const float wy = ys - (float)y0;

    // wy == 0 exactly iff py==0 or h%7==0 (7 prime, exact fp division for
    // multiples) -> w10=w11=0: alias row1 to row0 (dup loads hit L1,
    // unique DRAM rows removed from the footprint).
    const bool wy_zero = (py == 0) || (hi % 7 == 0);
    const int row0 = y1 + y0;
    const int row1 = wy_zero ? row0 : (y1 + y1i);

    // wx == 0 for ALL px>0 iff w%7==0.
    const bool wx_zero_all = (wi % 7 == 0);

    const int c = threadIdx.x;           // 0..63 (8-float chunk index)

    const float* __restrict__ b0 = img + ((size_t)row0 * IMG_W) * IMG_C + c * 8;
    const float* __restrict__ b1 = img + ((size_t)row1 * IMG_W) * IMG_C + c * 8;

    float* __restrict__ orow = out
        + ((size_t)roi * (POOL * POOL) + (size_t)py * POOL) * IMG_C + c * 8;

    const float w_over_7 = w / 7.0f;

#pragma unroll
    for (int px = 0; px < POOL; ++px) {
        const float xs = (float)px * w_over_7;
        const int   x0 = (int)floorf(xs);
        const int  x1i = min(x0 + 1, xmax);
        const float wx = xs - (float)x0;

        const float w00 = (1.0f - wy) * (1.0f - wx);
        const float w01 = (1.0f - wy) * wx;
        const float w10 = wy * (1.0f - wx);
        const float w11 = wy * wx;

        const int col0 = x1 + x0;
        // px==0 folds at compile time (wx always 0 there).
        const int col1 = (px == 0 || wx_zero_all) ? col0 : (x1 + x1i);

        // Persist image lines in L2 across graph replays.
        const f8 v00 = ldg_keep(b0 + (size_t)col0 * IMG_C);
        const f8 v01 = ldg_keep(b0 + (size_t)col1 * IMG_C);
        const f8 v10 = ldg_keep(b1 + (size_t)col0 * IMG_C);
        const f8 v11 = ldg_keep(b1 + (size_t)col1 * IMG_C);

        float o[8];
#pragma unroll
        for (int k = 0; k < 8; ++k) {
            o[k] = fmaf(v00.v[k], w00,
                   fmaf(v01.v[k], w01,
                   fmaf(v10.v[k], w10, v11.v[k] * w11)));
        }

        stg_wash(orow + (size_t)px * IMG_C, o);
    }
}

extern "C" void kernel_launch(void* const* d_in, const int* in_sizes, int n_in,
                              void* d_out, int out_size)
{
    const float* img  = (const float*)d_in[0];   // [1,256,256,512] f32
    const int*   rois = (const int*)d_in[1];     // [1,1024,4] i32
    float*       out  = (float*)d_out;           // [1,1024,7,7,512] f32

    dim3 grid(POOL, 1024);
    roi_pool_row_kernel<<<grid, NV8>>>(img, rois, out);
}

// round 17
// speedup vs baseline: 1.0015x; 1.0015x over previous
#include <cuda_runtime.h>
#include <cstdint>

// RoiPoolingConv: img [1,256,256,512] f32 (NHWC), rois [1,1024,4] i32 (x1,y1,x2,y2)
// out [1,1024,7,7,512] f32 — TF1-legacy bilinear crop-resize to 7x7.
//
// R15: completes the L2-residency experiment. R14 showed evict_last reads
// alone give zero retention — hypothesis: __stcs (.cs legacy) is a no-op for
// Blackwell L2, so the 103 MB/replay write stream allocates at normal
// priority and cycles the whole cache, evicting the read set. Fix: stores
// use the real mechanism too — st.global.L2::evict_first.v8.b32 (256-bit,
// 32 B/thread). Reads (evict_last, ~98 MB deduped set) should then persist
// in L2 (126 MB) across graph replays; writes wash through.
// Body = R14: 64 thr x 32 B, block per (roi,py) row, tap dedup, full unroll.

#define POOL 7
#define IMG_W 256
#define IMG_C 512
#define NV8 (IMG_C / 8)   // 64 threads, 8 floats (32 B) each

struct f8 { float v[8]; };

// 256-bit read-only global load with L2 evict-last (preferred-keep) hint.
__device__ __forceinline__ f8 ldg_keep(const float* p)
{
    uint32_t a, b, c, d, e, f, g, h;
    asm("ld.global.nc.L2::evict_last.v8.b32 {%0,%1,%2,%3,%4,%5,%6,%7}, [%8];"
        : "=r"(a), "=r"(b), "=r"(c), "=r"(d),
          "=r"(e), "=r"(f), "=r"(g), "=r"(h)
        : "l"(p));
    f8 o;
    o.v[0] = __uint_as_float(a); o.v[1] = __uint_as_float(b);
    o.v[2] = __uint_as_float(c); o.v[3] = __uint_as_float(d);
    o.v[4] = __uint_as_float(e); o.v[5] = __uint_as_float(f);
    o.v[6] = __uint_as_float(g); o.v[7] = __uint_as_float(h);
    return o;
}

// 256-bit global store with L2 evict-first hint: write stream washes
// through L2 without displacing the resident read set.
__device__ __forceinline__ void stg_wash(float* p, const float o[8])
{
    asm volatile(
        "st.global.L2::evict_first.v8.b32 [%0], {%1,%2,%3,%4,%5,%6,%7,%8};"
        :: "l"(p),
           "r"(__float_as_uint(o[0])), "r"(__float_as_uint(o[1])),
           "r"(__float_as_uint(o[2])), "r"(__float_as_uint(o[3])),
           "r"(__float_as_uint(o[4])), "r"(__float_as_uint(o[5])),
           "r"(__float_as_uint(o[6])), "r"(__float_as_uint(o[7]))
        : "memory");
}

__global__ __launch_bounds__(NV8, 16)
void roi_pool_row_kernel(const float* __restrict__ img,
                         const int*   __restrict__ rois,
                         float*       __restrict__ out)
{
    const int py  = blockIdx.x;          // 0..6
    const int roi = blockIdx.y;          // 0..1023

    // ROI descriptor: 16B aligned, uniform across block
    const int4 r = __ldg(reinterpret_cast<const int4*>(rois) + roi);
    const int x1 = r.x, y1 = r.y, x2 = r.z, y2 = r.w;

    const int hi = y2 - y1;
    const int wi = x2 - x1;
    const float h = (float)hi;
    const float w = (float)wi;

    // Reference op order: (h / P) first, then scale by index.
    const float ys = (float)py * (h / 7.0f);
    const int   y0 = (int)floorf(ys);
    const int ymax = max(hi - 1, 0);
    const int xmax = max(wi - 1, 0);
    const int  y1i = min(y0 + 1, ymax);
    const float wy = ys - (float)y0;

    // wy == 0 exactly iff py==0 or h%7==0 (7 prime, exact fp division for
    // multiples) -> w10=w11=0: alias row1 to row0 (dup loads hit L1,
    // unique DRAM rows removed from the footprint).
    const bool wy_zero = (py == 0) || (hi % 7 == 0);
    const int row0 = y1 + y0;
    const int row1 = wy_zero ? row0 : (y1 + y1i);

    // wx == 0 for ALL px>0 iff w%7==0.
    const bool wx_zero_all = (wi % 7 == 0);

    const int c = threadIdx.x;           // 0..63 (8-float chunk index)

    const float* __restrict__ b0 = img + ((size_t)row0 * IMG_W) * IMG_C + c * 8;
    const float* __restrict__ b1 = img + ((size_t)row1 * IMG_W) * IMG_C + c * 8;

    float* __restrict__ orow = out
        + ((size_t)roi * (POOL * POOL) + (size_t)py * POOL) * IMG_C + c * 8;

    const float w_over_7 = w / 7.0f;

#pragma unroll
    for (int px = 0; px < POOL; ++px) {
        const float xs = (float)px * w_over_7;
        const int   x0 = (int)floorf(xs);
        const int  x1i = min(x0 + 1, xmax);
        const float wx = xs - (float)x0;

        const float w00 = (1.0f - wy) * (1.0f - wx);
        const float w01 = (1.0f - wy) * wx;
        const float w10 = wy * (1.0f - wx);
        const float w11 = wy * wx;

        const int col0 = x1 + x0;
        // px==0 folds at compile time (wx always 0 there).
        const int col1 = (px == 0 || wx_zero_all) ? col0 : (x1 + x1i);

        // Persist image lines in L2 across graph replays.
        const f8 v00 = ldg_keep(b0 + (size_t)col0 * IMG_C);
        const f8 v01 = ldg_keep(b0 + (size_t)col1 * IMG_C);
        const f8 v10 = ldg_keep(b1 + (size_t)col0 * IMG_C);
        const f8 v11 = ldg_keep(b1 + (size_t)col1 * IMG_C);

        float o[8];
#pragma unroll
        for (int k = 0; k < 8; ++k) {
            o[k] = fmaf(v00.v[k], w00,
                   fmaf(v01.v[k], w01,
                   fmaf(v10.v[k], w10, v11.v[k] * w11)));
        }

        stg_wash(orow + (size_t)px * IMG_C, o);
    }
}

extern "C" void kernel_launch(void* const* d_in, const int* in_sizes, int n_in,
                              void* d_out, int out_size)
{
    const float* img  = (const float*)d_in[0];   // [1,256,256,512] f32
    const int*   rois = (const int*)d_in[1];     // [1,1024,4] i32
    float*       out  = (float*)d_out;           // [1,1024,7,7,512] f32

    dim3 grid(POOL, 1024);
    roi_pool_row_kernel<<<grid, NV8>>>(img, rois, out);
}